// round 1
// baseline (speedup 1.0000x reference)
#include <cuda_runtime.h>
#include <cstdint>

#define B_  4
#define S_  1024
#define D_  1024
#define H_  16
#define HD_ 64
#define M_  (B_ * S_)        // 4096 rows
#define TD_ (3 * D_)         // 3072
#define NEG_ 10000.0f

// Scratch (allocation-free rule: __device__ globals)
__device__ float g_qkv[(size_t)M_ * TD_];   // [B*S, 3D]  48 MB
__device__ float g_ctx[(size_t)M_ * D_];    // [B*S, D]   16 MB

// ---------------------------------------------------------------------------
// Register-tiled SGEMM: C[M,N] = A[M,K] @ W[K,N] + bias[N]
// BM=BN=128, BK=8, 256 threads, 8x8 per-thread microtile.
// M % 128 == 0, N % 128 == 0, K % 8 == 0 hold for all uses here.
// ---------------------------------------------------------------------------
template <int BM, int BN, int BK, int TM, int TN>
__global__ __launch_bounds__(256, 2) void sgemm_bias(
    const float* __restrict__ A, const float* __restrict__ W,
    const float* __restrict__ bias, float* __restrict__ C,
    int M, int N, int K)
{
    __shared__ float As[BK][BM];
    __shared__ float Bs[BK][BN];

    const int tid = threadIdx.x;
    const int block_row = blockIdx.y * BM;
    const int block_col = blockIdx.x * BN;

    const int trow = (tid / (BN / TN)) * TM;   // 0..120
    const int tcol = (tid % (BN / TN)) * TN;   // 0..120

    // A tile load: 128x8, float4 along K. tid -> (row = tid/2, col4 = tid%2)
    const int aRow = tid >> 1;
    const int aCol = (tid & 1) * 4;
    // B tile load: 8x128, float4 along N. tid -> (row = tid/32, col4 = tid%32)
    const int bRow = tid >> 5;
    const int bCol = (tid & 31) * 4;

    const float* Ab = A + (size_t)block_row * K;
    const float* Wb = W + block_col;

    float acc[TM][TN];
    #pragma unroll
    for (int i = 0; i < TM; i++)
        #pragma unroll
        for (int j = 0; j < TN; j++) acc[i][j] = 0.0f;

    for (int k0 = 0; k0 < K; k0 += BK) {
        float4 a4 = *reinterpret_cast<const float4*>(Ab + (size_t)aRow * K + k0 + aCol);
        As[aCol + 0][aRow] = a4.x;
        As[aCol + 1][aRow] = a4.y;
        As[aCol + 2][aRow] = a4.z;
        As[aCol + 3][aRow] = a4.w;
        float4 b4 = *reinterpret_cast<const float4*>(Wb + (size_t)(k0 + bRow) * N + bCol);
        *reinterpret_cast<float4*>(&Bs[bRow][bCol]) = b4;
        __syncthreads();

        #pragma unroll
        for (int kk = 0; kk < BK; kk++) {
            float regM[TM], regN[TN];
            #pragma unroll
            for (int i = 0; i < TM; i++) regM[i] = As[kk][trow + i];
            #pragma unroll
            for (int j = 0; j < TN; j++) regN[j] = Bs[kk][tcol + j];
            #pragma unroll
            for (int i = 0; i < TM; i++)
                #pragma unroll
                for (int j = 0; j < TN; j++)
                    acc[i][j] += regM[i] * regN[j];
        }
        __syncthreads();
    }

    #pragma unroll
    for (int i = 0; i < TM; i++) {
        float* crow = C + (size_t)(block_row + trow + i) * N + block_col + tcol;
        #pragma unroll
        for (int j = 0; j < TN; j += 4) {
            float4 o;
            o.x = acc[i][j + 0] + bias[block_col + tcol + j + 0];
            o.y = acc[i][j + 1] + bias[block_col + tcol + j + 1];
            o.z = acc[i][j + 2] + bias[block_col + tcol + j + 2];
            o.w = acc[i][j + 3] + bias[block_col + tcol + j + 3];
            *reinterpret_cast<float4*>(crow + j) = o;
        }
    }
}

// ---------------------------------------------------------------------------
// Attention: one block per (b, h, q-row). 128 threads.
// Reads q/k/v from g_qkv, writes probs to w_out [B,H,S,S], AV to g_ctx [B,S,D].
// ---------------------------------------------------------------------------
__global__ __launch_bounds__(128) void attn_kernel(
    const float* __restrict__ mask,   // [B,1,1,S] -> [B*S]
    float* __restrict__ w_out)        // [B,H,S,S]
{
    const int idx = blockIdx.x;           // b*H*S + h*S + qi
    const int qi = idx % S_;
    const int h  = (idx / S_) % H_;
    const int b  = idx / (S_ * H_);
    const int tid = threadIdx.x;

    __shared__ float q[HD_];
    __shared__ float sc[S_];
    __shared__ float red[4];
    __shared__ float accs[128];

    const float* qrow = g_qkv + (size_t)(b * S_ + qi) * TD_ + h * HD_;
    if (tid < HD_) q[tid] = qrow[tid];
    __syncthreads();

    const float* kbase = g_qkv + (size_t)b * S_ * TD_ + D_ + h * HD_;
    const float* vbase = g_qkv + (size_t)b * S_ * TD_ + 2 * D_ + h * HD_;
    const float* mrow  = mask + b * S_;
    const float scale = 0.125f;  // 1/sqrt(64)

    // scores
    for (int j = tid; j < S_; j += 128) {
        float s;
        if (j <= qi) {
            const float* krow = kbase + (size_t)j * TD_;
            float d = 0.0f;
            #pragma unroll
            for (int t = 0; t < HD_; t++) d += q[t] * krow[t];
            s = d * scale + mrow[j];
        } else {
            s = -NEG_ + mrow[j];
        }
        sc[j] = s;
    }
    __syncthreads();

    // row max
    float m = -1e30f;
    for (int j = tid; j < S_; j += 128) m = fmaxf(m, sc[j]);
    #pragma unroll
    for (int o = 16; o; o >>= 1) m = fmaxf(m, __shfl_xor_sync(0xffffffffu, m, o));
    if ((tid & 31) == 0) red[tid >> 5] = m;
    __syncthreads();
    m = fmaxf(fmaxf(red[0], red[1]), fmaxf(red[2], red[3]));

    // exp + sum
    float lsum = 0.0f;
    for (int j = tid; j < S_; j += 128) {
        float e = __expf(sc[j] - m);
        sc[j] = e;
        lsum += e;
    }
    #pragma unroll
    for (int o = 16; o; o >>= 1) lsum += __shfl_xor_sync(0xffffffffu, lsum, o);
    __syncthreads();                       // all reads of red (max) done
    if ((tid & 31) == 0) red[tid >> 5] = lsum;
    __syncthreads();
    const float inv = 1.0f / (red[0] + red[1] + red[2] + red[3]);

    // normalize + write probs
    float* wrow = w_out + (size_t)((b * H_ + h) * S_ + qi) * S_;
    for (int j = tid; j < S_; j += 128) {
        float p = sc[j] * inv;
        sc[j] = p;
        wrow[j] = p;
    }
    __syncthreads();

    // AV: thread t -> dim d = t&63, half = t>>6 splits the j range
    const int d = tid & 63;
    const int half = tid >> 6;
    float acc = 0.0f;
    for (int j = half; j <= qi; j += 2)
        acc += sc[j] * vbase[(size_t)j * TD_ + d];
    accs[tid] = acc;
    __syncthreads();
    if (tid < HD_)
        g_ctx[(size_t)(b * S_ + qi) * D_ + h * HD_ + tid] = accs[tid] + accs[tid + 64];
}

// ---------------------------------------------------------------------------
extern "C" void kernel_launch(void* const* d_in, const int* in_sizes, int n_in,
                              void* d_out, int out_size)
{
    const float* x      = (const float*)d_in[0];
    const float* mask   = (const float*)d_in[1];
    const float* w_attn = (const float*)d_in[2];
    const float* b_attn = (const float*)d_in[3];
    const float* w_proj = (const float*)d_in[4];
    const float* b_proj = (const float*)d_in[5];

    float* out   = (float*)d_out;
    float* a_out = out;                                  // [B,S,D]
    float* w_out = out + (size_t)M_ * D_;                // [B,H,S,S]

    float* qkv = nullptr;
    float* ctx = nullptr;
    cudaGetSymbolAddress((void**)&qkv, g_qkv);
    cudaGetSymbolAddress((void**)&ctx, g_ctx);

    // 1) QKV projection: [4096,1024] @ [1024,3072] + b
    {
        dim3 grid(TD_ / 128, M_ / 128);
        sgemm_bias<128, 128, 8, 8, 8><<<grid, 256>>>(x, w_attn, b_attn, qkv, M_, TD_, D_);
    }

    // 2) Attention (scores, softmax, probs out, AV)
    attn_kernel<<<B_ * H_ * S_, 128>>>(mask, w_out);

    // 3) Output projection: [4096,1024] @ [1024,1024] + b
    {
        dim3 grid(D_ / 128, M_ / 128);
        sgemm_bias<128, 128, 8, 8, 8><<<grid, 256>>>(ctx, w_proj, b_proj, a_out, M_, D_, D_);
    }
}

// round 3
// speedup vs baseline: 6.6887x; 6.6887x over previous
#include <cuda_runtime.h>
#include <cstdint>

#define B_  4
#define S_  1024
#define D_  1024
#define H_  16
#define HD_ 64
#define M_  (B_ * S_)        // 4096 rows
#define TD_ (3 * D_)         // 3072
#define NH_ (B_ * H_)        // 64 head-batches
#define NEG_ 10000.0f

// Scratch (allocation-free rule: __device__ globals)
__device__ float g_q[(size_t)NH_ * S_ * HD_];   // [B*H, S, 64] 16 MB
__device__ float g_k[(size_t)NH_ * S_ * HD_];
__device__ float g_v[(size_t)NH_ * S_ * HD_];
__device__ float g_ctx[(size_t)M_ * D_];        // [B*S, D]     16 MB

// ---------------------------------------------------------------------------
// QKV GEMM with head-scatter epilogue:
// C = x[4096,1024] @ w_attn[1024,3072] + b_attn, scattered into g_q/g_k/g_v
// layout [(b*H+h), s, hd].
// BM=BN=128, BK=8, 256 threads, 8x8 microtile.
// ---------------------------------------------------------------------------
__global__ __launch_bounds__(256, 2) void sgemm_qkv(
    const float* __restrict__ A, const float* __restrict__ W,
    const float* __restrict__ bias)
{
    const int K = D_, N = TD_;
    __shared__ float As[8][128];
    __shared__ float Bs[8][128];

    const int tid = threadIdx.x;
    const int block_row = blockIdx.y * 128;
    const int block_col = blockIdx.x * 128;
    const int trow = (tid >> 4) * 8;
    const int tcol = (tid & 15) * 8;

    const int aRow = tid >> 1;
    const int aCol = (tid & 1) * 4;
    const int bRow = tid >> 5;
    const int bCol = (tid & 31) * 4;

    const float* Ab = A + (size_t)block_row * K;
    const float* Wb = W + block_col;

    float acc[8][8];
    #pragma unroll
    for (int i = 0; i < 8; i++)
        #pragma unroll
        for (int j = 0; j < 8; j++) acc[i][j] = 0.0f;

    for (int k0 = 0; k0 < K; k0 += 8) {
        float4 a4 = *reinterpret_cast<const float4*>(Ab + (size_t)aRow * K + k0 + aCol);
        As[aCol + 0][aRow] = a4.x;
        As[aCol + 1][aRow] = a4.y;
        As[aCol + 2][aRow] = a4.z;
        As[aCol + 3][aRow] = a4.w;
        *reinterpret_cast<float4*>(&Bs[bRow][bCol]) =
            *reinterpret_cast<const float4*>(Wb + (size_t)(k0 + bRow) * N + bCol);
        __syncthreads();

        #pragma unroll
        for (int kk = 0; kk < 8; kk++) {
            float rM[8], rN[8];
            #pragma unroll
            for (int i = 0; i < 8; i++) rM[i] = As[kk][trow + i];
            #pragma unroll
            for (int j = 0; j < 8; j++) rN[j] = Bs[kk][tcol + j];
            #pragma unroll
            for (int i = 0; i < 8; i++)
                #pragma unroll
                for (int j = 0; j < 8; j++)
                    acc[i][j] += rM[i] * rN[j];
        }
        __syncthreads();
    }

    #pragma unroll
    for (int i = 0; i < 8; i++) {
        const int row = block_row + trow + i;
        const int b = row >> 10;
        const int s = row & (S_ - 1);
        #pragma unroll
        for (int j = 0; j < 8; j += 4) {
            const int col = block_col + tcol + j;
            const int part = col >> 10;            // 0=q,1=k,2=v
            const int within = col & (D_ - 1);
            const int h = within >> 6;
            const int hd = within & 63;
            float* dst = (part == 0 ? g_q : part == 1 ? g_k : g_v)
                       + ((size_t)(b * H_ + h) * S_ + s) * HD_ + hd;
            float4 o;
            o.x = acc[i][j + 0] + bias[col + 0];
            o.y = acc[i][j + 1] + bias[col + 1];
            o.z = acc[i][j + 2] + bias[col + 2];
            o.w = acc[i][j + 3] + bias[col + 3];
            *reinterpret_cast<float4*>(dst) = o;
        }
    }
}

// ---------------------------------------------------------------------------
// Scores: per head, lower-triangular 128x128 tiles of Q @ K^T * 0.125.
// blockIdx.y = head (b*H+h), blockIdx.x = tri index (0..35).
// Writes raw scores (pre-mask) into w_out[head, qi, kj]; diagonal tile gets
// -NEG above the diagonal. Upper tiles are never written (softmax synthesizes).
// ---------------------------------------------------------------------------
__global__ __launch_bounds__(256, 2) void scores_kernel(float* __restrict__ w_out)
{
    const int head = blockIdx.y;
    int t = blockIdx.x, qb = 0;
    while (t >= qb + 1) { t -= qb + 1; qb++; }
    const int kb = t;

    __shared__ float Qs[8][128];
    __shared__ float Ks[8][128];

    const int tid = threadIdx.x;
    const int trow = (tid >> 4) * 8;
    const int tcol = (tid & 15) * 8;
    const int lRow = tid >> 1;
    const int lCol = (tid & 1) * 4;

    const float* Qb = g_q + ((size_t)head * S_ + qb * 128) * HD_;
    const float* Kb = g_k + ((size_t)head * S_ + kb * 128) * HD_;

    float acc[8][8];
    #pragma unroll
    for (int i = 0; i < 8; i++)
        #pragma unroll
        for (int j = 0; j < 8; j++) acc[i][j] = 0.0f;

    for (int k0 = 0; k0 < HD_; k0 += 8) {
        float4 q4 = *reinterpret_cast<const float4*>(Qb + (size_t)lRow * HD_ + k0 + lCol);
        Qs[lCol + 0][lRow] = q4.x;
        Qs[lCol + 1][lRow] = q4.y;
        Qs[lCol + 2][lRow] = q4.z;
        Qs[lCol + 3][lRow] = q4.w;
        float4 k4 = *reinterpret_cast<const float4*>(Kb + (size_t)lRow * HD_ + k0 + lCol);
        Ks[lCol + 0][lRow] = k4.x;
        Ks[lCol + 1][lRow] = k4.y;
        Ks[lCol + 2][lRow] = k4.z;
        Ks[lCol + 3][lRow] = k4.w;
        __syncthreads();

        #pragma unroll
        for (int kk = 0; kk < 8; kk++) {
            float rM[8], rN[8];
            #pragma unroll
            for (int i = 0; i < 8; i++) rM[i] = Qs[kk][trow + i];
            #pragma unroll
            for (int j = 0; j < 8; j++) rN[j] = Ks[kk][tcol + j];
            #pragma unroll
            for (int i = 0; i < 8; i++)
                #pragma unroll
                for (int j = 0; j < 8; j++)
                    acc[i][j] += rM[i] * rN[j];
        }
        __syncthreads();
    }

    const bool diag = (qb == kb);
    #pragma unroll
    for (int i = 0; i < 8; i++) {
        const int qi = qb * 128 + trow + i;
        float* wrow = w_out + ((size_t)head * S_ + qi) * S_ + kb * 128 + tcol;
        #pragma unroll
        for (int j = 0; j < 8; j += 4) {
            float4 o;
            o.x = acc[i][j + 0] * 0.125f;
            o.y = acc[i][j + 1] * 0.125f;
            o.z = acc[i][j + 2] * 0.125f;
            o.w = acc[i][j + 3] * 0.125f;
            if (diag) {
                const int kj = kb * 128 + tcol + j;
                if (kj + 0 > qi) o.x = -NEG_;
                if (kj + 1 > qi) o.y = -NEG_;
                if (kj + 2 > qi) o.z = -NEG_;
                if (kj + 3 > qi) o.w = -NEG_;
            }
            *reinterpret_cast<float4*>(wrow + j) = o;
        }
    }
}

// ---------------------------------------------------------------------------
// Softmax over rows of w_out. One block (128 thr) per (head, qi).
// Stored scores exist for j <= qi (tile granularity: j < (qb+1)*128, but
// entries beyond qi in the diagonal tile hold -NEG already).
// For j >= tile end (never written) synthesize -NEG. Adds mask[b, j] to all.
// ---------------------------------------------------------------------------
__global__ __launch_bounds__(128) void softmax_kernel(
    const float* __restrict__ mask, float* __restrict__ w_out)
{
    const int idx = blockIdx.x;        // head*S + qi
    const int qi = idx & (S_ - 1);
    const int head = idx >> 10;
    const int b = head >> 4;
    const int tid = threadIdx.x;
    const int valid = ((qi >> 7) + 1) << 7;   // tile-rounded stored extent

    __shared__ float sc[S_];
    __shared__ float red[4];

    float* wrow = w_out + (size_t)idx * S_;
    const float* mrow = mask + b * S_;

    float m = -3.0e38f;
    for (int j = tid; j < S_; j += 128) {
        float s = (j < valid ? wrow[j] : -NEG_) + mrow[j];
        sc[j] = s;
        m = fmaxf(m, s);
    }
    #pragma unroll
    for (int o = 16; o; o >>= 1) m = fmaxf(m, __shfl_xor_sync(0xffffffffu, m, o));
    if ((tid & 31) == 0) red[tid >> 5] = m;
    __syncthreads();
    m = fmaxf(fmaxf(red[0], red[1]), fmaxf(red[2], red[3]));

    float lsum = 0.0f;
    for (int j = tid; j < S_; j += 128) {
        float e = __expf(sc[j] - m);
        sc[j] = e;
        lsum += e;
    }
    #pragma unroll
    for (int o = 16; o; o >>= 1) lsum += __shfl_xor_sync(0xffffffffu, lsum, o);
    __syncthreads();
    if ((tid & 31) == 0) red[tid >> 5] = lsum;
    __syncthreads();
    const float inv = 1.0f / (red[0] + red[1] + red[2] + red[3]);

    for (int j = tid * 4; j < S_; j += 128 * 4) {
        float4 o;
        o.x = sc[j + 0] * inv;
        o.y = sc[j + 1] * inv;
        o.z = sc[j + 2] * inv;
        o.w = sc[j + 3] * inv;
        *reinterpret_cast<float4*>(wrow + j) = o;
    }
}

// ---------------------------------------------------------------------------
// AV: per head, ctx[qrows, 64] = P[qrows, :kmax] @ V[:kmax, 64].
// blockIdx.y = head, blockIdx.x = qb (0..7, 128 rows each).
// Causal: P is exactly 0 for j > qi (softmax underflow), so K-loop stops at
// (qb+1)*128. Scatter into g_ctx [B,S,D] merged-head layout.
// BM=128, BN=64, BK=8; 256 threads; 8x4 microtile.
// ---------------------------------------------------------------------------
__global__ __launch_bounds__(256, 2) void av_kernel(const float* __restrict__ w_out)
{
    const int head = blockIdx.y;
    const int qb = blockIdx.x;
    const int b = head >> 4;
    const int h = head & 15;
    const int kmax = (qb + 1) * 128;

    __shared__ float Ps[8][128];
    __shared__ float Vs[8][64];

    const int tid = threadIdx.x;
    const int trow = (tid >> 4) * 8;
    const int tcol = (tid & 15) * 4;
    const int pRow = tid >> 1;
    const int pCol = (tid & 1) * 4;
    const int vRow = tid >> 4;          // 0..15 -> but only 8 rows; guard tid<128
    const int vCol = (tid & 15) * 4;

    const float* Pb = w_out + ((size_t)head * S_ + qb * 128) * S_;
    const float* Vb = g_v + (size_t)head * S_ * HD_;

    float acc[8][4];
    #pragma unroll
    for (int i = 0; i < 8; i++)
        #pragma unroll
        for (int j = 0; j < 4; j++) acc[i][j] = 0.0f;

    for (int k0 = 0; k0 < kmax; k0 += 8) {
        float4 p4 = *reinterpret_cast<const float4*>(Pb + (size_t)pRow * S_ + k0 + pCol);
        Ps[pCol + 0][pRow] = p4.x;
        Ps[pCol + 1][pRow] = p4.y;
        Ps[pCol + 2][pRow] = p4.z;
        Ps[pCol + 3][pRow] = p4.w;
        if (tid < 128)
            *reinterpret_cast<float4*>(&Vs[vRow][vCol]) =
                *reinterpret_cast<const float4*>(Vb + (size_t)(k0 + vRow) * HD_ + vCol);
        __syncthreads();

        #pragma unroll
        for (int kk = 0; kk < 8; kk++) {
            float rM[8], rN[4];
            #pragma unroll
            for (int i = 0; i < 8; i++) rM[i] = Ps[kk][trow + i];
            #pragma unroll
            for (int j = 0; j < 4; j++) rN[j] = Vs[kk][tcol + j];
            #pragma unroll
            for (int i = 0; i < 8; i++)
                #pragma unroll
                for (int j = 0; j < 4; j++)
                    acc[i][j] += rM[i] * rN[j];
        }
        __syncthreads();
    }

    #pragma unroll
    for (int i = 0; i < 8; i++) {
        const int s = qb * 128 + trow + i;
        float4 o;
        o.x = acc[i][0]; o.y = acc[i][1]; o.z = acc[i][2]; o.w = acc[i][3];
        *reinterpret_cast<float4*>(
            g_ctx + ((size_t)(b * S_ + s)) * D_ + h * HD_ + tcol) = o;
    }
}

// ---------------------------------------------------------------------------
// Standard SGEMM + bias for the output projection.
// ---------------------------------------------------------------------------
__global__ __launch_bounds__(256, 2) void sgemm_bias(
    const float* __restrict__ A, const float* __restrict__ W,
    const float* __restrict__ bias, float* __restrict__ C,
    int M, int N, int K)
{
    __shared__ float As[8][128];
    __shared__ float Bs[8][128];

    const int tid = threadIdx.x;
    const int block_row = blockIdx.y * 128;
    const int block_col = blockIdx.x * 128;
    const int trow = (tid >> 4) * 8;
    const int tcol = (tid & 15) * 8;
    const int aRow = tid >> 1;
    const int aCol = (tid & 1) * 4;
    const int bRow = tid >> 5;
    const int bCol = (tid & 31) * 4;

    const float* Ab = A + (size_t)block_row * K;
    const float* Wb = W + block_col;

    float acc[8][8];
    #pragma unroll
    for (int i = 0; i < 8; i++)
        #pragma unroll
        for (int j = 0; j < 8; j++) acc[i][j] = 0.0f;

    for (int k0 = 0; k0 < K; k0 += 8) {
        float4 a4 = *reinterpret_cast<const float4*>(Ab + (size_t)aRow * K + k0 + aCol);
        As[aCol + 0][aRow] = a4.x;
        As[aCol + 1][aRow] = a4.y;
        As[aCol + 2][aRow] = a4.z;
        As[aCol + 3][aRow] = a4.w;
        *reinterpret_cast<float4*>(&Bs[bRow][bCol]) =
            *reinterpret_cast<const float4*>(Wb + (size_t)(k0 + bRow) * N + bCol);
        __syncthreads();

        #pragma unroll
        for (int kk = 0; kk < 8; kk++) {
            float rM[8], rN[8];
            #pragma unroll
            for (int i = 0; i < 8; i++) rM[i] = As[kk][trow + i];
            #pragma unroll
            for (int j = 0; j < 8; j++) rN[j] = Bs[kk][tcol + j];
            #pragma unroll
            for (int i = 0; i < 8; i++)
                #pragma unroll
                for (int j = 0; j < 8; j++)
                    acc[i][j] += rM[i] * rN[j];
        }
        __syncthreads();
    }

    #pragma unroll
    for (int i = 0; i < 8; i++) {
        float* crow = C + (size_t)(block_row + trow + i) * N + block_col + tcol;
        #pragma unroll
        for (int j = 0; j < 8; j += 4) {
            float4 o;
            o.x = acc[i][j + 0] + bias[block_col + tcol + j + 0];
            o.y = acc[i][j + 1] + bias[block_col + tcol + j + 1];
            o.z = acc[i][j + 2] + bias[block_col + tcol + j + 2];
            o.w = acc[i][j + 3] + bias[block_col + tcol + j + 3];
            *reinterpret_cast<float4*>(crow + j) = o;
        }
    }
}

// ---------------------------------------------------------------------------
extern "C" void kernel_launch(void* const* d_in, const int* in_sizes, int n_in,
                              void* d_out, int out_size)
{
    const float* x      = (const float*)d_in[0];
    const float* mask   = (const float*)d_in[1];
    const float* w_attn = (const float*)d_in[2];
    const float* b_attn = (const float*)d_in[3];
    const float* w_proj = (const float*)d_in[4];
    const float* b_proj = (const float*)d_in[5];

    float* out   = (float*)d_out;
    float* a_out = out;                         // [B,S,D]
    float* w_out = out + (size_t)M_ * D_;       // [B,H,S,S]

    float* ctx = nullptr;
    cudaGetSymbolAddress((void**)&ctx, g_ctx);

    // 1) QKV projection with head scatter
    {
        dim3 grid(TD_ / 128, M_ / 128);
        sgemm_qkv<<<grid, 256>>>(x, w_attn, b_attn);
    }
    // 2) Scores (lower-tri tiles only)
    {
        dim3 grid(36, NH_);
        scores_kernel<<<grid, 256>>>(w_out);
    }
    // 3) Softmax + mask, writes probs (full rows)
    softmax_kernel<<<NH_ * S_, 128>>>(mask, w_out);
    // 4) AV with causal K-truncation
    {
        dim3 grid(S_ / 128, NH_);
        av_kernel<<<grid, 256>>>(w_out);
    }
    // 5) Output projection
    {
        dim3 grid(D_ / 128, M_ / 128);
        sgemm_bias<<<grid, 256>>>(ctx, w_proj, b_proj, a_out, M_, D_, D_);
    }
}

// round 5
// speedup vs baseline: 10.5641x; 1.5794x over previous
#include <cuda_runtime.h>
#include <cuda_bf16.h>
#include <cstdint>

#define B_  4
#define S_  1024
#define D_  1024
#define H_  16
#define HD_ 64
#define M_  (B_ * S_)        // 4096 rows
#define TD_ (3 * D_)         // 3072
#define NH_ (B_ * H_)        // 64 head-batches
#define NEG_ 10000.0f

// ---------------------------------------------------------------------------
// Scratch (allocation-free rule: __device__ globals)
// ---------------------------------------------------------------------------
__device__ float g_q[(size_t)NH_ * S_ * HD_];    // [B*H, S, 64] fp32
__device__ float g_k[(size_t)NH_ * S_ * HD_];
__device__ float g_v[(size_t)NH_ * S_ * HD_];
__device__ float g_ctx[(size_t)M_ * D_];         // [B*S, D] fp32

__device__ __nv_bfloat16 g_xh[(size_t)M_ * D_];  // x hi/lo, row-major
__device__ __nv_bfloat16 g_xl[(size_t)M_ * D_];
__device__ __nv_bfloat16 g_wah[(size_t)TD_ * D_]; // w_attn^T hi/lo [3072][1024]
__device__ __nv_bfloat16 g_wal[(size_t)TD_ * D_];
__device__ __nv_bfloat16 g_wph[(size_t)D_ * D_];  // w_proj^T hi/lo [1024][1024]
__device__ __nv_bfloat16 g_wpl[(size_t)D_ * D_];
__device__ __nv_bfloat16 g_ch[(size_t)M_ * D_];   // ctx hi/lo row-major
__device__ __nv_bfloat16 g_cl[(size_t)M_ * D_];

__device__ __forceinline__ uint32_t smem_u32(const void* p) {
    uint32_t a;
    asm("{ .reg .u64 t; cvta.to.shared.u64 t, %1; cvt.u32.u64 %0, t; }" : "=r"(a) : "l"(p));
    return a;
}

// ---------------------------------------------------------------------------
// Conversion kernels: fp32 -> bf16 hi/lo (split compensation)
// ---------------------------------------------------------------------------
__global__ __launch_bounds__(256) void convert_rm(
    const float* __restrict__ in, __nv_bfloat16* __restrict__ oh,
    __nv_bfloat16* __restrict__ ol, size_t n)
{
    size_t i = ((size_t)blockIdx.x * 256 + threadIdx.x) * 4;
    if (i >= n) return;
    float4 v = *reinterpret_cast<const float4*>(in + i);
    __nv_bfloat16 h0 = __float2bfloat16(v.x), h1 = __float2bfloat16(v.y);
    __nv_bfloat16 h2 = __float2bfloat16(v.z), h3 = __float2bfloat16(v.w);
    __nv_bfloat162 hh0 = __halves2bfloat162(h0, h1);
    __nv_bfloat162 hh1 = __halves2bfloat162(h2, h3);
    __nv_bfloat162 ll0 = __halves2bfloat162(
        __float2bfloat16(v.x - __bfloat162float(h0)),
        __float2bfloat16(v.y - __bfloat162float(h1)));
    __nv_bfloat162 ll1 = __halves2bfloat162(
        __float2bfloat16(v.z - __bfloat162float(h2)),
        __float2bfloat16(v.w - __bfloat162float(h3)));
    *reinterpret_cast<__nv_bfloat162*>(oh + i)     = hh0;
    *reinterpret_cast<__nv_bfloat162*>(oh + i + 2) = hh1;
    *reinterpret_cast<__nv_bfloat162*>(ol + i)     = ll0;
    *reinterpret_cast<__nv_bfloat162*>(ol + i + 2) = ll1;
}

__global__ __launch_bounds__(256) void convert_transpose(
    const float* __restrict__ in, __nv_bfloat16* __restrict__ oh,
    __nv_bfloat16* __restrict__ ol, int R, int C)
{
    __shared__ float t[32][33];
    const int c0 = blockIdx.x * 32, r0 = blockIdx.y * 32;
    const int tx = threadIdx.x & 31, ty = threadIdx.x >> 5;   // 32 x 8
    #pragma unroll
    for (int i = 0; i < 32; i += 8)
        t[ty + i][tx] = in[(size_t)(r0 + ty + i) * C + c0 + tx];
    __syncthreads();
    #pragma unroll
    for (int i = 0; i < 32; i += 8) {
        float v = t[tx][ty + i];
        __nv_bfloat16 h = __float2bfloat16(v);
        oh[(size_t)(c0 + ty + i) * R + r0 + tx] = h;
        ol[(size_t)(c0 + ty + i) * R + r0 + tx] =
            __float2bfloat16(v - __bfloat162float(h));
    }
}

// ---------------------------------------------------------------------------
// mma.sync bf16x3 GEMM: C[m,n] = sum_k A[m,k]*B[n,k]  (A,B K-major bf16 hi/lo)
// CTA 128x128, 8 warps of 32x64, K-chunk 32, cp.async double buffer.
// mode 0: QKV head-scatter epilogue; mode 1: plain store + bias to Cout.
// ---------------------------------------------------------------------------
#define ROWB 80                    // padded row bytes (32 bf16 data + 16B pad)
#define TILEB (128 * ROWB)         // 10240 bytes per tile
#define STG_BYTES (4 * TILEB)      // Ah, Al, Bh, Bl per stage
#define GEMM_SMEM (2 * STG_BYTES)  // 81920

__device__ __forceinline__ void ldm_x4(uint32_t* f, uint32_t addr) {
    asm volatile("ldmatrix.sync.aligned.m8n8.x4.shared.b16 {%0,%1,%2,%3}, [%4];"
                 : "=r"(f[0]), "=r"(f[1]), "=r"(f[2]), "=r"(f[3]) : "r"(addr));
}
__device__ __forceinline__ void mma_bf16(float* d, const uint32_t* a,
                                         uint32_t b0, uint32_t b1) {
    asm volatile("mma.sync.aligned.m16n8k16.row.col.f32.bf16.bf16.f32 "
                 "{%0,%1,%2,%3}, {%4,%5,%6,%7}, {%8,%9}, {%0,%1,%2,%3};"
                 : "+f"(d[0]), "+f"(d[1]), "+f"(d[2]), "+f"(d[3])
                 : "r"(a[0]), "r"(a[1]), "r"(a[2]), "r"(a[3]), "r"(b0), "r"(b1));
}

__global__ __launch_bounds__(256, 1) void gemm_mma_bf16x3(
    const __nv_bfloat16* __restrict__ Ah, const __nv_bfloat16* __restrict__ Al,
    const __nv_bfloat16* __restrict__ Bh, const __nv_bfloat16* __restrict__ Bl,
    const float* __restrict__ bias, float* __restrict__ Cout,
    int Kdim, int Ncols, int mode)
{
    extern __shared__ char smem[];
    const uint32_t sb = smem_u32(smem);
    const int tid = threadIdx.x;
    const int lane = tid & 31;
    const int wid = tid >> 5;
    const int wm = wid & 3;           // warp row: 32*wm
    const int wn = wid >> 2;          // warp col: 64*wn
    const int block_row = blockIdx.y * 128;
    const int block_col = blockIdx.x * 128;

    const __nv_bfloat16* srcs[4] = {
        Ah + (size_t)block_row * Kdim, Al + (size_t)block_row * Kdim,
        Bh + (size_t)block_col * Kdim, Bl + (size_t)block_col * Kdim};

    float acc[2][8][4];
    #pragma unroll
    for (int i = 0; i < 2; i++)
        #pragma unroll
        for (int j = 0; j < 8; j++)
            #pragma unroll
            for (int q = 0; q < 4; q++) acc[i][j][q] = 0.0f;

    const int nch = Kdim / 32;

    // chunk issue: 4 tiles x 128 rows x 4 x 16B = 2048 cp.asyncs, 8 per thread
    auto issue = [&](int c) {
        const int k0 = c * 32;
        const uint32_t stage = sb + (uint32_t)(c & 1) * STG_BYTES;
        #pragma unroll
        for (int t = 0; t < 8; t++) {
            int idx = tid + t * 256;
            int tile = idx >> 9;
            int r = (idx >> 2) & 127;
            int ch = idx & 3;
            const __nv_bfloat16* g = srcs[tile] + (size_t)r * Kdim + k0 + ch * 8;
            uint32_t s = stage + (uint32_t)tile * TILEB + (uint32_t)r * ROWB + ch * 16;
            asm volatile("cp.async.ca.shared.global [%0], [%1], 16;"
                         :: "r"(s), "l"(g));
        }
        asm volatile("cp.async.commit_group;");
    };

    issue(0);

    const int g8 = lane >> 3;          // ldmatrix address group 0..3
    const int r8 = lane & 7;

    for (int c = 0; c < nch; c++) {
        if (c + 1 < nch) {
            issue(c + 1);
            asm volatile("cp.async.wait_group 1;");
        } else {
            asm volatile("cp.async.wait_group 0;");
        }
        __syncthreads();
        const uint32_t stage = sb + (uint32_t)(c & 1) * STG_BYTES;

        #pragma unroll
        for (int kk = 0; kk < 2; kk++) {
            // A fragments (Ah, Al): 2 m16 tiles each
            uint32_t ah[2][4], al[2][4];
            #pragma unroll
            for (int i = 0; i < 2; i++) {
                // groups: g0 rows m0-7 k0, g1 rows m8-15 k0, g2 rows m0-7 k8, g3 rows m8-15 k8
                uint32_t row = wm * 32 + i * 16 + r8 + ((g8 & 1) << 3);
                uint32_t colb = kk * 32 + ((g8 >> 1) << 4);
                uint32_t a = stage + row * ROWB + colb;
                ldm_x4(ah[i], a);
                ldm_x4(al[i], a + TILEB);
            }
            // B fragments: 4 n16 blocks, each ldmatrix.x4 covers 2 n8 tiles
            #pragma unroll
            for (int jj = 0; jj < 4; jj++) {
                // groups: g0 (n0-7,k0), g1 (n0-7,k8), g2 (n8-15,k0), g3 (n8-15,k8)
                uint32_t nrow = wn * 64 + jj * 16 + r8 + ((g8 >> 1) << 3);
                uint32_t colb = kk * 32 + ((g8 & 1) << 4);
                uint32_t bptr = stage + 2 * TILEB + nrow * ROWB + colb;
                uint32_t bh[4], bl[4];
                ldm_x4(bh, bptr);
                ldm_x4(bl, bptr + TILEB);
                #pragma unroll
                for (int i = 0; i < 2; i++) {
                    mma_bf16(acc[i][2 * jj + 0], ah[i], bh[0], bh[1]);
                    mma_bf16(acc[i][2 * jj + 0], ah[i], bl[0], bl[1]);
                    mma_bf16(acc[i][2 * jj + 0], al[i], bh[0], bh[1]);
                    mma_bf16(acc[i][2 * jj + 1], ah[i], bh[2], bh[3]);
                    mma_bf16(acc[i][2 * jj + 1], ah[i], bl[2], bl[3]);
                    mma_bf16(acc[i][2 * jj + 1], al[i], bh[2], bh[3]);
                }
            }
        }
        __syncthreads();
    }

    // epilogue: acc[i][j] covers rows (wm*32+16i + lane/4, +8), cols (wn*64+8j + (lane%4)*2)
    #pragma unroll
    for (int i = 0; i < 2; i++) {
        #pragma unroll
        for (int j = 0; j < 8; j++) {
            const int r0 = block_row + wm * 32 + i * 16 + (lane >> 2);
            const int n0 = block_col + wn * 64 + j * 8 + (lane & 3) * 2;
            const float bx = bias[n0], by = bias[n0 + 1];
            float2 lo = make_float2(acc[i][j][0] + bx, acc[i][j][1] + by);
            float2 hi = make_float2(acc[i][j][2] + bx, acc[i][j][3] + by);
            if (mode == 1) {
                *reinterpret_cast<float2*>(Cout + (size_t)r0 * Ncols + n0) = lo;
                *reinterpret_cast<float2*>(Cout + (size_t)(r0 + 8) * Ncols + n0) = hi;
            } else {
                const int part = n0 >> 10;
                const int within = n0 & (D_ - 1);
                const int h = within >> 6;
                const int hd = within & 63;
                float* base = (part == 0 ? g_q : part == 1 ? g_k : g_v);
                const int b0r = r0 >> 10, s0 = r0 & (S_ - 1);
                *reinterpret_cast<float2*>(
                    base + ((size_t)((b0r << 4) + h) * S_ + s0) * HD_ + hd) = lo;
                const int r1 = r0 + 8;
                const int b1r = r1 >> 10, s1 = r1 & (S_ - 1);
                *reinterpret_cast<float2*>(
                    base + ((size_t)((b1r << 4) + h) * S_ + s1) * HD_ + hd) = hi;
            }
        }
    }
}

// ---------------------------------------------------------------------------
// Scores: lower-triangular 128x128 tiles of Q @ K^T * 0.125 (fp32 FFMA)
// ---------------------------------------------------------------------------
__global__ __launch_bounds__(256, 2) void scores_kernel(float* __restrict__ w_out)
{
    const int head = blockIdx.y;
    int t = blockIdx.x, qb = 0;
    while (t >= qb + 1) { t -= qb + 1; qb++; }
    const int kb = t;

    __shared__ float Qs[8][128];
    __shared__ float Ks[8][128];

    const int tid = threadIdx.x;
    const int trow = (tid >> 4) * 8;
    const int tcol = (tid & 15) * 8;
    const int lRow = tid >> 1;
    const int lCol = (tid & 1) * 4;

    const float* Qb = g_q + ((size_t)head * S_ + qb * 128) * HD_;
    const float* Kb = g_k + ((size_t)head * S_ + kb * 128) * HD_;

    float acc[8][8];
    #pragma unroll
    for (int i = 0; i < 8; i++)
        #pragma unroll
        for (int j = 0; j < 8; j++) acc[i][j] = 0.0f;

    for (int k0 = 0; k0 < HD_; k0 += 8) {
        float4 q4 = *reinterpret_cast<const float4*>(Qb + (size_t)lRow * HD_ + k0 + lCol);
        Qs[lCol + 0][lRow] = q4.x;
        Qs[lCol + 1][lRow] = q4.y;
        Qs[lCol + 2][lRow] = q4.z;
        Qs[lCol + 3][lRow] = q4.w;
        float4 k4 = *reinterpret_cast<const float4*>(Kb + (size_t)lRow * HD_ + k0 + lCol);
        Ks[lCol + 0][lRow] = k4.x;
        Ks[lCol + 1][lRow] = k4.y;
        Ks[lCol + 2][lRow] = k4.z;
        Ks[lCol + 3][lRow] = k4.w;
        __syncthreads();

        #pragma unroll
        for (int kk = 0; kk < 8; kk++) {
            float rM[8], rN[8];
            #pragma unroll
            for (int i = 0; i < 8; i++) rM[i] = Qs[kk][trow + i];
            #pragma unroll
            for (int j = 0; j < 8; j++) rN[j] = Ks[kk][tcol + j];
            #pragma unroll
            for (int i = 0; i < 8; i++)
                #pragma unroll
                for (int j = 0; j < 8; j++)
                    acc[i][j] += rM[i] * rN[j];
        }
        __syncthreads();
    }

    const bool diag = (qb == kb);
    #pragma unroll
    for (int i = 0; i < 8; i++) {
        const int qi = qb * 128 + trow + i;
        float* wrow = w_out + ((size_t)head * S_ + qi) * S_ + kb * 128 + tcol;
        #pragma unroll
        for (int j = 0; j < 8; j += 4) {
            float4 o;
            o.x = acc[i][j + 0] * 0.125f;
            o.y = acc[i][j + 1] * 0.125f;
            o.z = acc[i][j + 2] * 0.125f;
            o.w = acc[i][j + 3] * 0.125f;
            if (diag) {
                const int kj = kb * 128 + tcol + j;
                if (kj + 0 > qi) o.x = -NEG_;
                if (kj + 1 > qi) o.y = -NEG_;
                if (kj + 2 > qi) o.z = -NEG_;
                if (kj + 3 > qi) o.w = -NEG_;
            }
            *reinterpret_cast<float4*>(wrow + j) = o;
        }
    }
}

// ---------------------------------------------------------------------------
// Softmax over rows of w_out
// ---------------------------------------------------------------------------
__global__ __launch_bounds__(128) void softmax_kernel(
    const float* __restrict__ mask, float* __restrict__ w_out)
{
    const int idx = blockIdx.x;
    const int qi = idx & (S_ - 1);
    const int head = idx >> 10;
    const int b = head >> 4;
    const int tid = threadIdx.x;
    const int valid = ((qi >> 7) + 1) << 7;

    __shared__ float sc[S_];
    __shared__ float red[4];

    float* wrow = w_out + (size_t)idx * S_;
    const float* mrow = mask + b * S_;

    float m = -3.0e38f;
    for (int j = tid; j < S_; j += 128) {
        float s = (j < valid ? wrow[j] : -NEG_) + mrow[j];
        sc[j] = s;
        m = fmaxf(m, s);
    }
    #pragma unroll
    for (int o = 16; o; o >>= 1) m = fmaxf(m, __shfl_xor_sync(0xffffffffu, m, o));
    if ((tid & 31) == 0) red[tid >> 5] = m;
    __syncthreads();
    m = fmaxf(fmaxf(red[0], red[1]), fmaxf(red[2], red[3]));

    float lsum = 0.0f;
    for (int j = tid; j < S_; j += 128) {
        float e = __expf(sc[j] - m);
        sc[j] = e;
        lsum += e;
    }
    #pragma unroll
    for (int o = 16; o; o >>= 1) lsum += __shfl_xor_sync(0xffffffffu, lsum, o);
    __syncthreads();
    if ((tid & 31) == 0) red[tid >> 5] = lsum;
    __syncthreads();
    const float inv = 1.0f / (red[0] + red[1] + red[2] + red[3]);

    for (int j = tid * 4; j < S_; j += 128 * 4) {
        float4 o;
        o.x = sc[j + 0] * inv;
        o.y = sc[j + 1] * inv;
        o.z = sc[j + 2] * inv;
        o.w = sc[j + 3] * inv;
        *reinterpret_cast<float4*>(wrow + j) = o;
    }
}

// ---------------------------------------------------------------------------
// AV with causal K-truncation, writes g_ctx fp32
// ---------------------------------------------------------------------------
__global__ __launch_bounds__(256, 2) void av_kernel(const float* __restrict__ w_out)
{
    const int head = blockIdx.y;
    const int qb = blockIdx.x;
    const int b = head >> 4;
    const int h = head & 15;
    const int kmax = (qb + 1) * 128;

    __shared__ float Ps[8][128];
    __shared__ float Vs[8][64];

    const int tid = threadIdx.x;
    const int trow = (tid >> 4) * 8;
    const int tcol = (tid & 15) * 4;
    const int pRow = tid >> 1;
    const int pCol = (tid & 1) * 4;
    const int vRow = tid >> 4;
    const int vCol = (tid & 15) * 4;

    const float* Pb = w_out + ((size_t)head * S_ + qb * 128) * S_;
    const float* Vb = g_v + (size_t)head * S_ * HD_;

    float acc[8][4];
    #pragma unroll
    for (int i = 0; i < 8; i++)
        #pragma unroll
        for (int j = 0; j < 4; j++) acc[i][j] = 0.0f;

    for (int k0 = 0; k0 < kmax; k0 += 8) {
        float4 p4 = *reinterpret_cast<const float4*>(Pb + (size_t)pRow * S_ + k0 + pCol);
        Ps[pCol + 0][pRow] = p4.x;
        Ps[pCol + 1][pRow] = p4.y;
        Ps[pCol + 2][pRow] = p4.z;
        Ps[pCol + 3][pRow] = p4.w;
        if (tid < 128)
            *reinterpret_cast<float4*>(&Vs[vRow][vCol]) =
                *reinterpret_cast<const float4*>(Vb + (size_t)(k0 + vRow) * HD_ + vCol);
        __syncthreads();

        #pragma unroll
        for (int kk = 0; kk < 8; kk++) {
            float rM[8], rN[4];
            #pragma unroll
            for (int i = 0; i < 8; i++) rM[i] = Ps[kk][trow + i];
            #pragma unroll
            for (int j = 0; j < 4; j++) rN[j] = Vs[kk][tcol + j];
            #pragma unroll
            for (int i = 0; i < 8; i++)
                #pragma unroll
                for (int j = 0; j < 4; j++)
                    acc[i][j] += rM[i] * rN[j];
        }
        __syncthreads();
    }

    #pragma unroll
    for (int i = 0; i < 8; i++) {
        const int s = qb * 128 + trow + i;
        float4 o;
        o.x = acc[i][0]; o.y = acc[i][1]; o.z = acc[i][2]; o.w = acc[i][3];
        *reinterpret_cast<float4*>(
            g_ctx + ((size_t)(b * S_ + s)) * D_ + h * HD_ + tcol) = o;
    }
}

// ---------------------------------------------------------------------------
extern "C" void kernel_launch(void* const* d_in, const int* in_sizes, int n_in,
                              void* d_out, int out_size)
{
    const float* x      = (const float*)d_in[0];
    const float* mask   = (const float*)d_in[1];
    const float* w_attn = (const float*)d_in[2];
    const float* b_attn = (const float*)d_in[3];
    const float* w_proj = (const float*)d_in[4];
    const float* b_proj = (const float*)d_in[5];

    float* out   = (float*)d_out;
    float* a_out = out;                         // [B,S,D]
    float* w_out = out + (size_t)M_ * D_;       // [B,H,S,S]

    float* ctx = nullptr;
    cudaGetSymbolAddress((void**)&ctx, g_ctx);
    __nv_bfloat16 *xh, *xl, *wah, *wal, *wph, *wpl, *ch, *cl;
    cudaGetSymbolAddress((void**)&xh,  g_xh);
    cudaGetSymbolAddress((void**)&xl,  g_xl);
    cudaGetSymbolAddress((void**)&wah, g_wah);
    cudaGetSymbolAddress((void**)&wal, g_wal);
    cudaGetSymbolAddress((void**)&wph, g_wph);
    cudaGetSymbolAddress((void**)&wpl, g_wpl);
    cudaGetSymbolAddress((void**)&ch,  g_ch);
    cudaGetSymbolAddress((void**)&cl,  g_cl);

    cudaFuncSetAttribute(gemm_mma_bf16x3,
                         cudaFuncAttributeMaxDynamicSharedMemorySize, GEMM_SMEM);

    // 1) converts
    convert_rm<<<(M_ * D_ / 4 + 255) / 256, 256>>>(x, xh, xl, (size_t)M_ * D_);
    convert_transpose<<<dim3(TD_ / 32, D_ / 32), 256>>>(w_attn, wah, wal, D_, TD_);
    convert_transpose<<<dim3(D_ / 32, D_ / 32), 256>>>(w_proj, wph, wpl, D_, D_);

    // 2) QKV GEMM (mma.sync bf16x3) with head-scatter
    gemm_mma_bf16x3<<<dim3(TD_ / 128, M_ / 128), 256, GEMM_SMEM>>>(
        xh, xl, wah, wal, b_attn, nullptr, D_, TD_, 0);

    // 3) Scores (lower-tri), softmax, AV
    scores_kernel<<<dim3(36, NH_), 256>>>(w_out);
    softmax_kernel<<<NH_ * S_, 128>>>(mask, w_out);
    av_kernel<<<dim3(S_ / 128, NH_), 256>>>(w_out);

    // 4) ctx -> bf16 hi/lo, proj GEMM
    convert_rm<<<(M_ * D_ / 4 + 255) / 256, 256>>>(ctx, ch, cl, (size_t)M_ * D_);
    gemm_mma_bf16x3<<<dim3(D_ / 128, M_ / 128), 256, GEMM_SMEM>>>(
        ch, cl, wph, wpl, b_proj, a_out, D_, D_, 1);
}

// round 6
// speedup vs baseline: 14.3225x; 1.3558x over previous
#include <cuda_runtime.h>
#include <cuda_bf16.h>
#include <cstdint>

#define B_  4
#define S_  1024
#define D_  1024
#define H_  16
#define HD_ 64
#define M_  (B_ * S_)        // 4096 rows
#define TD_ (3 * D_)         // 3072
#define NH_ (B_ * H_)        // 64 head-batches
#define NEG_ 10000.0f

// ---------------------------------------------------------------------------
// Scratch (allocation-free rule: __device__ globals)
// ---------------------------------------------------------------------------
__device__ __nv_bfloat16 g_qh[(size_t)NH_ * S_ * HD_];  // [head, s, 64]
__device__ __nv_bfloat16 g_ql[(size_t)NH_ * S_ * HD_];
__device__ __nv_bfloat16 g_kh[(size_t)NH_ * S_ * HD_];
__device__ __nv_bfloat16 g_kl[(size_t)NH_ * S_ * HD_];
__device__ __nv_bfloat16 g_vh[(size_t)NH_ * S_ * HD_];
__device__ __nv_bfloat16 g_vl[(size_t)NH_ * S_ * HD_];
__device__ __nv_bfloat16 g_ph[(size_t)NH_ * S_ * S_];   // probs hi/lo [head, qi, j]
__device__ __nv_bfloat16 g_pl[(size_t)NH_ * S_ * S_];
__device__ __nv_bfloat16 g_ch[(size_t)M_ * D_];          // ctx hi/lo row-major
__device__ __nv_bfloat16 g_cl[(size_t)M_ * D_];

__device__ __nv_bfloat16 g_xh[(size_t)M_ * D_];          // x hi/lo row-major
__device__ __nv_bfloat16 g_xl[(size_t)M_ * D_];
__device__ __nv_bfloat16 g_wah[(size_t)TD_ * D_];        // w_attn^T hi/lo
__device__ __nv_bfloat16 g_wal[(size_t)TD_ * D_];
__device__ __nv_bfloat16 g_wph[(size_t)D_ * D_];         // w_proj^T hi/lo
__device__ __nv_bfloat16 g_wpl[(size_t)D_ * D_];

__device__ __forceinline__ uint32_t smem_u32(const void* p) {
    uint32_t a;
    asm("{ .reg .u64 t; cvta.to.shared.u64 t, %1; cvt.u32.u64 %0, t; }" : "=r"(a) : "l"(p));
    return a;
}
__device__ __forceinline__ void cp16(uint32_t s, const void* g) {
    asm volatile("cp.async.ca.shared.global [%0], [%1], 16;" :: "r"(s), "l"(g));
}
__device__ __forceinline__ void ldm_x4(uint32_t* f, uint32_t addr) {
    asm volatile("ldmatrix.sync.aligned.m8n8.x4.shared.b16 {%0,%1,%2,%3}, [%4];"
                 : "=r"(f[0]), "=r"(f[1]), "=r"(f[2]), "=r"(f[3]) : "r"(addr));
}
__device__ __forceinline__ void ldm_x4_t(uint32_t* f, uint32_t addr) {
    asm volatile("ldmatrix.sync.aligned.m8n8.x4.trans.shared.b16 {%0,%1,%2,%3}, [%4];"
                 : "=r"(f[0]), "=r"(f[1]), "=r"(f[2]), "=r"(f[3]) : "r"(addr));
}
__device__ __forceinline__ void mma_bf16(float* d, const uint32_t* a,
                                         uint32_t b0, uint32_t b1) {
    asm volatile("mma.sync.aligned.m16n8k16.row.col.f32.bf16.bf16.f32 "
                 "{%0,%1,%2,%3}, {%4,%5,%6,%7}, {%8,%9}, {%0,%1,%2,%3};"
                 : "+f"(d[0]), "+f"(d[1]), "+f"(d[2]), "+f"(d[3])
                 : "r"(a[0]), "r"(a[1]), "r"(a[2]), "r"(a[3]), "r"(b0), "r"(b1));
}
__device__ __forceinline__ void split_store(__nv_bfloat16* ph, __nv_bfloat16* pl,
                                            float2 v) {
    __nv_bfloat16 hx = __float2bfloat16(v.x), hy = __float2bfloat16(v.y);
    *reinterpret_cast<__nv_bfloat162*>(ph) = __halves2bfloat162(hx, hy);
    *reinterpret_cast<__nv_bfloat162*>(pl) = __halves2bfloat162(
        __float2bfloat16(v.x - __bfloat162float(hx)),
        __float2bfloat16(v.y - __bfloat162float(hy)));
}

// ---------------------------------------------------------------------------
// Conversion kernels
// ---------------------------------------------------------------------------
__global__ __launch_bounds__(256) void convert_rm(
    const float* __restrict__ in, __nv_bfloat16* __restrict__ oh,
    __nv_bfloat16* __restrict__ ol, size_t n)
{
    size_t i = ((size_t)blockIdx.x * 256 + threadIdx.x) * 4;
    if (i >= n) return;
    float4 v = *reinterpret_cast<const float4*>(in + i);
    split_store(oh + i, ol + i, make_float2(v.x, v.y));
    split_store(oh + i + 2, ol + i + 2, make_float2(v.z, v.w));
}

__global__ __launch_bounds__(256) void convert_transpose(
    const float* __restrict__ in, __nv_bfloat16* __restrict__ oh,
    __nv_bfloat16* __restrict__ ol, int R, int C)
{
    __shared__ float t[32][33];
    const int c0 = blockIdx.x * 32, r0 = blockIdx.y * 32;
    const int tx = threadIdx.x & 31, ty = threadIdx.x >> 5;
    #pragma unroll
    for (int i = 0; i < 32; i += 8)
        t[ty + i][tx] = in[(size_t)(r0 + ty + i) * C + c0 + tx];
    __syncthreads();
    #pragma unroll
    for (int i = 0; i < 32; i += 8) {
        float v = t[tx][ty + i];
        __nv_bfloat16 h = __float2bfloat16(v);
        oh[(size_t)(c0 + ty + i) * R + r0 + tx] = h;
        ol[(size_t)(c0 + ty + i) * R + r0 + tx] =
            __float2bfloat16(v - __bfloat162float(h));
    }
}

// ---------------------------------------------------------------------------
// mma.sync bf16x3 GEMM, CTA 128x128, 8 warps 32x64, K-chunk 32, cp.async x2.
// mode 0: QKV epilogue -> bf16 hi/lo q/k/v [head,s,64]
// mode 1: fp32 + bias -> Cout
// ---------------------------------------------------------------------------
#define ROWB 80
#define TILEB (128 * ROWB)
#define STG_BYTES (4 * TILEB)
#define GEMM_SMEM (2 * STG_BYTES)

__global__ __launch_bounds__(256, 1) void gemm_mma_bf16x3(
    const __nv_bfloat16* __restrict__ Ah, const __nv_bfloat16* __restrict__ Al,
    const __nv_bfloat16* __restrict__ Bh, const __nv_bfloat16* __restrict__ Bl,
    const float* __restrict__ bias, float* __restrict__ Cout,
    int Kdim, int Ncols, int mode)
{
    extern __shared__ char smem[];
    const uint32_t sb = smem_u32(smem);
    const int tid = threadIdx.x;
    const int lane = tid & 31;
    const int wid = tid >> 5;
    const int wm = wid & 3;
    const int wn = wid >> 2;
    const int block_row = blockIdx.y * 128;
    const int block_col = blockIdx.x * 128;

    const __nv_bfloat16* srcs[4] = {
        Ah + (size_t)block_row * Kdim, Al + (size_t)block_row * Kdim,
        Bh + (size_t)block_col * Kdim, Bl + (size_t)block_col * Kdim};

    float acc[2][8][4];
    #pragma unroll
    for (int i = 0; i < 2; i++)
        #pragma unroll
        for (int j = 0; j < 8; j++)
            #pragma unroll
            for (int q = 0; q < 4; q++) acc[i][j][q] = 0.0f;

    const int nch = Kdim / 32;

    auto issue = [&](int c) {
        const int k0 = c * 32;
        const uint32_t stage = sb + (uint32_t)(c & 1) * STG_BYTES;
        #pragma unroll
        for (int t = 0; t < 8; t++) {
            int idx = tid + t * 256;
            int tile = idx >> 9;
            int r = (idx >> 2) & 127;
            int ch = idx & 3;
            const __nv_bfloat16* g = srcs[tile] + (size_t)r * Kdim + k0 + ch * 8;
            cp16(stage + (uint32_t)tile * TILEB + (uint32_t)r * ROWB + ch * 16, g);
        }
        asm volatile("cp.async.commit_group;");
    };

    issue(0);

    const int g8 = lane >> 3;
    const int r8 = lane & 7;

    for (int c = 0; c < nch; c++) {
        if (c + 1 < nch) {
            issue(c + 1);
            asm volatile("cp.async.wait_group 1;");
        } else {
            asm volatile("cp.async.wait_group 0;");
        }
        __syncthreads();
        const uint32_t stage = sb + (uint32_t)(c & 1) * STG_BYTES;

        #pragma unroll
        for (int kk = 0; kk < 2; kk++) {
            uint32_t ah[2][4], al[2][4];
            #pragma unroll
            for (int i = 0; i < 2; i++) {
                uint32_t row = wm * 32 + i * 16 + r8 + ((g8 & 1) << 3);
                uint32_t colb = kk * 32 + ((g8 >> 1) << 4);
                uint32_t a = stage + row * ROWB + colb;
                ldm_x4(ah[i], a);
                ldm_x4(al[i], a + TILEB);
            }
            #pragma unroll
            for (int jj = 0; jj < 4; jj++) {
                uint32_t nrow = wn * 64 + jj * 16 + r8 + ((g8 >> 1) << 3);
                uint32_t colb = kk * 32 + ((g8 & 1) << 4);
                uint32_t bptr = stage + 2 * TILEB + nrow * ROWB + colb;
                uint32_t bh[4], bl[4];
                ldm_x4(bh, bptr);
                ldm_x4(bl, bptr + TILEB);
                #pragma unroll
                for (int i = 0; i < 2; i++) {
                    mma_bf16(acc[i][2 * jj + 0], ah[i], bh[0], bh[1]);
                    mma_bf16(acc[i][2 * jj + 0], ah[i], bl[0], bl[1]);
                    mma_bf16(acc[i][2 * jj + 0], al[i], bh[0], bh[1]);
                    mma_bf16(acc[i][2 * jj + 1], ah[i], bh[2], bh[3]);
                    mma_bf16(acc[i][2 * jj + 1], ah[i], bl[2], bl[3]);
                    mma_bf16(acc[i][2 * jj + 1], al[i], bh[2], bh[3]);
                }
            }
        }
        __syncthreads();
    }

    #pragma unroll
    for (int i = 0; i < 2; i++) {
        #pragma unroll
        for (int j = 0; j < 8; j++) {
            const int r0 = block_row + wm * 32 + i * 16 + (lane >> 2);
            const int n0 = block_col + wn * 64 + j * 8 + (lane & 3) * 2;
            const float bx = bias[n0], by = bias[n0 + 1];
            float2 lo = make_float2(acc[i][j][0] + bx, acc[i][j][1] + by);
            float2 hi = make_float2(acc[i][j][2] + bx, acc[i][j][3] + by);
            if (mode == 1) {
                *reinterpret_cast<float2*>(Cout + (size_t)r0 * Ncols + n0) = lo;
                *reinterpret_cast<float2*>(Cout + (size_t)(r0 + 8) * Ncols + n0) = hi;
            } else {
                const int part = n0 >> 10;
                const int within = n0 & (D_ - 1);
                const int h = within >> 6;
                const int hd = within & 63;
                __nv_bfloat16* bh_ = (part == 0 ? g_qh : part == 1 ? g_kh : g_vh);
                __nv_bfloat16* bl_ = (part == 0 ? g_ql : part == 1 ? g_kl : g_vl);
                const int b0r = r0 >> 10, s0 = r0 & (S_ - 1);
                size_t off0 = ((size_t)((b0r << 4) + h) * S_ + s0) * HD_ + hd;
                split_store(bh_ + off0, bl_ + off0, lo);
                const int r1 = r0 + 8;
                const int b1r = r1 >> 10, s1 = r1 & (S_ - 1);
                size_t off1 = ((size_t)((b1r << 4) + h) * S_ + s1) * HD_ + hd;
                split_store(bh_ + off1, bl_ + off1, hi);
            }
        }
    }
}

// ---------------------------------------------------------------------------
// Scores via HMMA bf16x3: per (head, lower-tri 128x128 tile).
// Q [m=qi,k=hd] row-major; K [n=kj,k=hd] K-major. One-shot K=64.
// ---------------------------------------------------------------------------
#define ROW2 144
#define STILE (128 * ROW2)     // 18432
#define SC_SMEM (4 * STILE)    // 73728

__global__ __launch_bounds__(256) void scores_mma(float* __restrict__ w_out)
{
    extern __shared__ char smem[];
    const uint32_t sb = smem_u32(smem);
    const int head = blockIdx.y;
    int t = blockIdx.x, qb = 0;
    while (t >= qb + 1) { t -= qb + 1; qb++; }
    const int kb = t;

    const int tid = threadIdx.x;
    const int lane = tid & 31;
    const int wid = tid >> 5;
    const int wm = wid & 3;
    const int wn = wid >> 2;
    const int g8 = lane >> 3;
    const int r8 = lane & 7;

    const __nv_bfloat16* srcs[4] = {
        g_qh + ((size_t)head * S_ + qb * 128) * HD_,
        g_ql + ((size_t)head * S_ + qb * 128) * HD_,
        g_kh + ((size_t)head * S_ + kb * 128) * HD_,
        g_kl + ((size_t)head * S_ + kb * 128) * HD_};

    #pragma unroll
    for (int tt = 0; tt < 16; tt++) {
        int idx = tid + tt * 256;
        int tile = idx >> 10;
        int r = (idx >> 3) & 127;
        int ch = idx & 7;
        cp16(sb + (uint32_t)tile * STILE + (uint32_t)r * ROW2 + ch * 16,
             srcs[tile] + (size_t)r * HD_ + ch * 8);
    }
    asm volatile("cp.async.commit_group;");
    asm volatile("cp.async.wait_group 0;");
    __syncthreads();

    float acc[2][8][4];
    #pragma unroll
    for (int i = 0; i < 2; i++)
        #pragma unroll
        for (int j = 0; j < 8; j++)
            #pragma unroll
            for (int q = 0; q < 4; q++) acc[i][j][q] = 0.0f;

    #pragma unroll
    for (int kk = 0; kk < 4; kk++) {
        uint32_t ah[2][4], al[2][4];
        #pragma unroll
        for (int i = 0; i < 2; i++) {
            uint32_t row = wm * 32 + i * 16 + r8 + ((g8 & 1) << 3);
            uint32_t colb = kk * 32 + ((g8 >> 1) << 4);
            uint32_t a = sb + row * ROW2 + colb;
            ldm_x4(ah[i], a);
            ldm_x4(al[i], a + STILE);
        }
        #pragma unroll
        for (int jj = 0; jj < 4; jj++) {
            uint32_t nrow = wn * 64 + jj * 16 + r8 + ((g8 >> 1) << 3);
            uint32_t colb = kk * 32 + ((g8 & 1) << 4);
            uint32_t bptr = sb + 2 * STILE + nrow * ROW2 + colb;
            uint32_t bh[4], bl[4];
            ldm_x4(bh, bptr);
            ldm_x4(bl, bptr + STILE);
            #pragma unroll
            for (int i = 0; i < 2; i++) {
                mma_bf16(acc[i][2 * jj + 0], ah[i], bh[0], bh[1]);
                mma_bf16(acc[i][2 * jj + 0], ah[i], bl[0], bl[1]);
                mma_bf16(acc[i][2 * jj + 0], al[i], bh[0], bh[1]);
                mma_bf16(acc[i][2 * jj + 1], ah[i], bh[2], bh[3]);
                mma_bf16(acc[i][2 * jj + 1], ah[i], bl[2], bl[3]);
                mma_bf16(acc[i][2 * jj + 1], al[i], bh[2], bh[3]);
            }
        }
    }

    const bool diag = (qb == kb);
    #pragma unroll
    for (int i = 0; i < 2; i++) {
        #pragma unroll
        for (int j = 0; j < 8; j++) {
            const int qi0 = qb * 128 + wm * 32 + i * 16 + (lane >> 2);
            const int kj = kb * 128 + wn * 64 + j * 8 + (lane & 3) * 2;
            float2 lo = make_float2(acc[i][j][0] * 0.125f, acc[i][j][1] * 0.125f);
            float2 hi = make_float2(acc[i][j][2] * 0.125f, acc[i][j][3] * 0.125f);
            if (diag) {
                if (kj + 0 > qi0) lo.x = -NEG_;
                if (kj + 1 > qi0) lo.y = -NEG_;
                if (kj + 0 > qi0 + 8) hi.x = -NEG_;
                if (kj + 1 > qi0 + 8) hi.y = -NEG_;
            }
            *reinterpret_cast<float2*>(
                w_out + ((size_t)head * S_ + qi0) * S_ + kj) = lo;
            *reinterpret_cast<float2*>(
                w_out + ((size_t)head * S_ + qi0 + 8) * S_ + kj) = hi;
        }
    }
}

// ---------------------------------------------------------------------------
// Softmax: 256 threads per row, register float4. Writes fp32 probs to w_out
// and bf16 hi/lo probs to g_ph/g_pl (valid prefix only).
// ---------------------------------------------------------------------------
__global__ __launch_bounds__(256) void softmax_kernel(
    const float* __restrict__ mask, float* __restrict__ w_out)
{
    const int idx = blockIdx.x;        // head*S + qi
    const int qi = idx & (S_ - 1);
    const int head = idx >> 10;
    const int b = head >> 4;
    const int tid = threadIdx.x;
    const int j0 = tid * 4;
    const int valid = ((qi >> 7) + 1) << 7;

    __shared__ float redm[8], reds[8];

    float* wrow = w_out + (size_t)idx * S_;
    const float* mrow = mask + b * S_;

    float4 s4;
    if (j0 < valid) s4 = *reinterpret_cast<const float4*>(wrow + j0);
    else            s4 = make_float4(-NEG_, -NEG_, -NEG_, -NEG_);
    float4 m4 = *reinterpret_cast<const float4*>(mrow + j0);
    s4.x += m4.x; s4.y += m4.y; s4.z += m4.z; s4.w += m4.w;

    float m = fmaxf(fmaxf(s4.x, s4.y), fmaxf(s4.z, s4.w));
    #pragma unroll
    for (int o = 16; o; o >>= 1) m = fmaxf(m, __shfl_xor_sync(0xffffffffu, m, o));
    if ((tid & 31) == 0) redm[tid >> 5] = m;
    __syncthreads();
    #pragma unroll
    for (int w = 0; w < 8; w++) m = fmaxf(m, redm[w]);

    float4 e4;
    e4.x = __expf(s4.x - m); e4.y = __expf(s4.y - m);
    e4.z = __expf(s4.z - m); e4.w = __expf(s4.w - m);
    float lsum = e4.x + e4.y + e4.z + e4.w;
    #pragma unroll
    for (int o = 16; o; o >>= 1) lsum += __shfl_xor_sync(0xffffffffu, lsum, o);
    if ((tid & 31) == 0) reds[tid >> 5] = lsum;
    __syncthreads();
    float total = 0.0f;
    #pragma unroll
    for (int w = 0; w < 8; w++) total += reds[w];
    const float inv = 1.0f / total;

    float4 p4;
    p4.x = e4.x * inv; p4.y = e4.y * inv; p4.z = e4.z * inv; p4.w = e4.w * inv;
    *reinterpret_cast<float4*>(wrow + j0) = p4;

    if (j0 < valid) {
        size_t off = (size_t)idx * S_ + j0;
        split_store(g_ph + off,     g_pl + off,     make_float2(p4.x, p4.y));
        split_store(g_ph + off + 2, g_pl + off + 2, make_float2(p4.z, p4.w));
    }
}

// ---------------------------------------------------------------------------
// AV via HMMA bf16x3: per (head, qb). M=128 q rows, N=64 dims, K=kmax.
// P [m=qi,k=j] row-major (g_ph/g_pl); V [k=s,n=d] loaded via trans-ldmatrix.
// K-chunk 64 double-buffered. Epilogue writes ctx bf16 hi/lo.
// ---------------------------------------------------------------------------
#define AV_P  18432              // P tile bytes (128 x 144)
#define AV_V  9216               // V tile bytes (64 x 144)
#define AV_STG (2 * AV_P + 2 * AV_V)   // 55296
#define AV_SMEM (2 * AV_STG)           // 110592

__global__ __launch_bounds__(256) void av_mma()
{
    extern __shared__ char smem[];
    const uint32_t sb = smem_u32(smem);
    const int head = blockIdx.y;
    const int qb = 7 - blockIdx.x;     // big tiles first
    const int b = head >> 4;
    const int h = head & 15;

    const int tid = threadIdx.x;
    const int lane = tid & 31;
    const int wid = tid >> 5;
    const int wm = wid & 3;
    const int wn = wid >> 2;
    const int g8 = lane >> 3;
    const int r8 = lane & 7;

    const __nv_bfloat16* Phb = g_ph + ((size_t)head * S_ + qb * 128) * S_;
    const __nv_bfloat16* Plb = g_pl + ((size_t)head * S_ + qb * 128) * S_;
    const __nv_bfloat16* Vhb = g_vh + (size_t)head * S_ * HD_;
    const __nv_bfloat16* Vlb = g_vl + (size_t)head * S_ * HD_;

    const int nch = 2 * (qb + 1);      // K-chunks of 64

    auto issue = [&](int c) {
        const int k0 = c * 64;
        const uint32_t stage = sb + (uint32_t)(c & 1) * AV_STG;
        #pragma unroll
        for (int t = 0; t < 12; t++) {
            int idx = tid + t * 256;
            if (idx < 2048) {
                int tile = idx >> 10;              // 0 Ph, 1 Pl
                int r = (idx >> 3) & 127;
                int ch = idx & 7;
                const __nv_bfloat16* g = (tile ? Plb : Phb) + (size_t)r * S_ + k0 + ch * 8;
                cp16(stage + (uint32_t)tile * AV_P + (uint32_t)r * ROW2 + ch * 16, g);
            } else {
                int v = idx - 2048;
                int tile = v >> 9;                 // 0 Vh, 1 Vl
                int r = (v >> 3) & 63;
                int ch = v & 7;
                const __nv_bfloat16* g = (tile ? Vlb : Vhb) + (size_t)(k0 + r) * HD_ + ch * 8;
                cp16(stage + 2 * AV_P + (uint32_t)tile * AV_V + (uint32_t)r * ROW2 + ch * 16, g);
            }
        }
        asm volatile("cp.async.commit_group;");
    };

    float acc[2][4][4];
    #pragma unroll
    for (int i = 0; i < 2; i++)
        #pragma unroll
        for (int j = 0; j < 4; j++)
            #pragma unroll
            for (int q = 0; q < 4; q++) acc[i][j][q] = 0.0f;

    issue(0);
    for (int c = 0; c < nch; c++) {
        if (c + 1 < nch) {
            issue(c + 1);
            asm volatile("cp.async.wait_group 1;");
        } else {
            asm volatile("cp.async.wait_group 0;");
        }
        __syncthreads();
        const uint32_t stage = sb + (uint32_t)(c & 1) * AV_STG;

        #pragma unroll
        for (int kk = 0; kk < 4; kk++) {
            uint32_t ph[2][4], pl[2][4];
            #pragma unroll
            for (int i = 0; i < 2; i++) {
                uint32_t row = wm * 32 + i * 16 + r8 + ((g8 & 1) << 3);
                uint32_t colb = kk * 32 + ((g8 >> 1) << 4);
                uint32_t a = stage + row * ROW2 + colb;
                ldm_x4(ph[i], a);
                ldm_x4(pl[i], a + AV_P);
            }
            #pragma unroll
            for (int jj = 0; jj < 2; jj++) {
                // trans ldmatrix on V [k,n]: rows = k, col bytes = n*2
                uint32_t row = kk * 16 + r8 + ((g8 & 1) << 3);
                uint32_t colb = (wn * 32 + jj * 16 + ((g8 >> 1) << 3)) * 2;
                uint32_t bptr = stage + 2 * AV_P + row * ROW2 + colb;
                uint32_t bh[4], bl[4];
                ldm_x4_t(bh, bptr);
                ldm_x4_t(bl, bptr + AV_V);
                #pragma unroll
                for (int i = 0; i < 2; i++) {
                    mma_bf16(acc[i][2 * jj + 0], ph[i], bh[0], bh[1]);
                    mma_bf16(acc[i][2 * jj + 0], ph[i], bl[0], bl[1]);
                    mma_bf16(acc[i][2 * jj + 0], pl[i], bh[0], bh[1]);
                    mma_bf16(acc[i][2 * jj + 1], ph[i], bh[2], bh[3]);
                    mma_bf16(acc[i][2 * jj + 1], ph[i], bl[2], bl[3]);
                    mma_bf16(acc[i][2 * jj + 1], pl[i], bh[2], bh[3]);
                }
            }
        }
        __syncthreads();
    }

    // epilogue -> ctx bf16 hi/lo at [b*S+s, h*64+d]
    #pragma unroll
    for (int i = 0; i < 2; i++) {
        #pragma unroll
        for (int j = 0; j < 4; j++) {
            const int s0 = qb * 128 + wm * 32 + i * 16 + (lane >> 2);
            const int d0 = wn * 32 + j * 8 + (lane & 3) * 2;
            float2 lo = make_float2(acc[i][j][0], acc[i][j][1]);
            float2 hi = make_float2(acc[i][j][2], acc[i][j][3]);
            size_t off0 = (size_t)(b * S_ + s0) * D_ + h * HD_ + d0;
            split_store(g_ch + off0, g_cl + off0, lo);
            size_t off1 = (size_t)(b * S_ + s0 + 8) * D_ + h * HD_ + d0;
            split_store(g_ch + off1, g_cl + off1, hi);
        }
    }
}

// ---------------------------------------------------------------------------
extern "C" void kernel_launch(void* const* d_in, const int* in_sizes, int n_in,
                              void* d_out, int out_size)
{
    const float* x      = (const float*)d_in[0];
    const float* mask   = (const float*)d_in[1];
    const float* w_attn = (const float*)d_in[2];
    const float* b_attn = (const float*)d_in[3];
    const float* w_proj = (const float*)d_in[4];
    const float* b_proj = (const float*)d_in[5];

    float* out   = (float*)d_out;
    float* a_out = out;                         // [B,S,D]
    float* w_out = out + (size_t)M_ * D_;       // [B,H,S,S]

    __nv_bfloat16 *xh, *xl, *wah, *wal, *wph, *wpl, *ch, *cl;
    cudaGetSymbolAddress((void**)&xh,  g_xh);
    cudaGetSymbolAddress((void**)&xl,  g_xl);
    cudaGetSymbolAddress((void**)&wah, g_wah);
    cudaGetSymbolAddress((void**)&wal, g_wal);
    cudaGetSymbolAddress((void**)&wph, g_wph);
    cudaGetSymbolAddress((void**)&wpl, g_wpl);
    cudaGetSymbolAddress((void**)&ch,  g_ch);
    cudaGetSymbolAddress((void**)&cl,  g_cl);

    cudaFuncSetAttribute(gemm_mma_bf16x3,
                         cudaFuncAttributeMaxDynamicSharedMemorySize, GEMM_SMEM);
    cudaFuncSetAttribute(scores_mma,
                         cudaFuncAttributeMaxDynamicSharedMemorySize, SC_SMEM);
    cudaFuncSetAttribute(av_mma,
                         cudaFuncAttributeMaxDynamicSharedMemorySize, AV_SMEM);

    // 1) converts
    convert_rm<<<(M_ * D_ / 4 + 255) / 256, 256>>>(x, xh, xl, (size_t)M_ * D_);
    convert_transpose<<<dim3(TD_ / 32, D_ / 32), 256>>>(w_attn, wah, wal, D_, TD_);
    convert_transpose<<<dim3(D_ / 32, D_ / 32), 256>>>(w_proj, wph, wpl, D_, D_);

    // 2) QKV GEMM -> bf16 hi/lo q/k/v
    gemm_mma_bf16x3<<<dim3(TD_ / 128, M_ / 128), 256, GEMM_SMEM>>>(
        xh, xl, wah, wal, b_attn, nullptr, D_, TD_, 0);

    // 3) Scores (HMMA, lower-tri) -> softmax (emits bf16 P) -> AV (HMMA)
    scores_mma<<<dim3(36, NH_), 256, SC_SMEM>>>(w_out);
    softmax_kernel<<<NH_ * S_, 256>>>(mask, w_out);
    av_mma<<<dim3(8, NH_), 256, AV_SMEM>>>();

    // 4) Output projection
    gemm_mma_bf16x3<<<dim3(D_ / 128, M_ / 128), 256, GEMM_SMEM>>>(
        ch, cl, wph, wpl, b_proj, a_out, D_, D_, 1);
}